// round 3
// baseline (speedup 1.0000x reference)
#include <cuda_runtime.h>

typedef unsigned long long ull;

#define N_ 128
#define L_ 160
#define E_ 512
#define HE_ 512
#define HD_ 1024
#define T_ 128
#define LN_ (L_*N_)
#define G4E_ 2048
#define NB_ 128u   // persistent grid size (single wave)

// ---------------- scratch (device globals) ----------------
__device__ __align__(16) float g_xs[LN_*E_];
__device__ __align__(16) float g_G[2][(size_t)LN_*G4E_];
__device__ __align__(16) float g_h1[(size_t)LN_*2*HE_];
__device__ __align__(16) float g_enc[(size_t)LN_*2*HE_];
__device__ __align__(16) float g_eh[2][2][N_*HE_];   // [phase][dir] enc h state
__device__ __align__(16) float g_ec[2][N_*HE_];      // [dir] enc c state
__device__ __align__(16) float g_dh[2][N_*HD_];      // dec h ping-pong
__device__ __align__(16) float g_dc[N_*HD_];
__device__ int   g_amax[N_];
__device__ float g_lterm[L_*N_];

__device__ unsigned g_bcnt = 0;
__device__ volatile unsigned g_bgen = 0;

__device__ __forceinline__ void fma2(ull& d, ull a, ull b){
    asm("fma.rn.f32x2 %0, %1, %2, %0;" : "+l"(d) : "l"(a), "l"(b));
}
__device__ __forceinline__ float2 unpack2(ull v){
    float2 r; asm("mov.b64 {%0, %1}, %2;" : "=f"(r.x), "=f"(r.y) : "l"(v)); return r;
}
__device__ __forceinline__ float sigf(float x){ return 1.f/(1.f+expf(-x)); }

// grid-wide barrier: all NB_ blocks resident (single wave)
__device__ __forceinline__ void gridbar(){
    __syncthreads();
    if (threadIdx.x == 0) {
        unsigned g = g_bgen;
        __threadfence();
        if (atomicAdd(&g_bcnt, 1u) == NB_ - 1u) {
            atomicExch(&g_bcnt, 0u);
            __threadfence();
            g_bgen = g + 1u;
        } else {
            while (g_bgen == g) { }
        }
        __threadfence();
    }
    __syncthreads();
}

// ---------------- embedding lookup ----------------
__global__ void k_embed(const int* __restrict__ ids, const float* __restrict__ embed)
{
    int i = blockIdx.x*blockDim.x + threadIdx.x;
    const int tot = LN_*E_/4;
    if (i >= tot) return;
    int e4 = i % (E_/4);
    int ln = i / (E_/4);
    int l = ln / N_, n = ln % N_;
    int id = ids[n*L_ + l];
    reinterpret_cast<float4*>(g_xs)[i] =
        reinterpret_cast<const float4*>(embed + (size_t)id*E_)[e4];
}

// ---------------- big GEMM: C[z] = A(M x K) @ B[z](2048 x K)^T + bias, f32x2 ----------------
__global__ __launch_bounds__(256) void k_gemm_bias(int asel, const float* __restrict__ Ball,
                                                   const float* __restrict__ biasall, int K)
{
    const float* A = asel ? g_h1 : g_xs;
    int z = blockIdx.z;
    const float* B = Ball + (size_t)z * G4E_ * K;
    const float* bias = biasall + z * G4E_;
    float* C = g_G[z];
    int m0 = blockIdx.y * 128, n0 = blockIdx.x * 128;
    __shared__ float2 As2[8][132];   // duplicated {a,a} pairs
    __shared__ float  Bs[8][132];
    int tid = threadIdx.x;
    int lr = tid >> 1, lk = (tid & 1) * 4;
    int ry = (tid >> 4) * 8, cx = (tid & 15) * 8;
    ull acc[8][4];
    #pragma unroll
    for (int i = 0; i < 8; i++)
        #pragma unroll
        for (int j = 0; j < 4; j++) acc[i][j] = 0ull;
    const float* Arow = A + (size_t)(m0+lr)*K + lk;
    const float* Brow = B + (size_t)(n0+lr)*K + lk;
    for (int kc = 0; kc < K; kc += 8) {
        float4 av = *(const float4*)(Arow + kc);
        float4 bv = *(const float4*)(Brow + kc);
        __syncthreads();
        As2[lk+0][lr]=make_float2(av.x,av.x); As2[lk+1][lr]=make_float2(av.y,av.y);
        As2[lk+2][lr]=make_float2(av.z,av.z); As2[lk+3][lr]=make_float2(av.w,av.w);
        Bs[lk+0][lr]=bv.x; Bs[lk+1][lr]=bv.y; Bs[lk+2][lr]=bv.z; Bs[lk+3][lr]=bv.w;
        __syncthreads();
        #pragma unroll
        for (int kk = 0; kk < 8; kk++) {
            ulonglong2 a01 = *(const ulonglong2*)&As2[kk][ry+0];
            ulonglong2 a23 = *(const ulonglong2*)&As2[kk][ry+2];
            ulonglong2 a45 = *(const ulonglong2*)&As2[kk][ry+4];
            ulonglong2 a67 = *(const ulonglong2*)&As2[kk][ry+6];
            ulonglong2 b01 = *(const ulonglong2*)&Bs[kk][cx];
            ulonglong2 b23 = *(const ulonglong2*)&Bs[kk][cx+4];
            ull a[8] = {a01.x,a01.y,a23.x,a23.y,a45.x,a45.y,a67.x,a67.y};
            #pragma unroll
            for (int i = 0; i < 8; i++) {
                fma2(acc[i][0], a[i], b01.x);
                fma2(acc[i][1], a[i], b01.y);
                fma2(acc[i][2], a[i], b23.x);
                fma2(acc[i][3], a[i], b23.y);
            }
        }
    }
    #pragma unroll
    for (int i = 0; i < 8; i++) {
        float* Cp = C + (size_t)(m0+ry+i)*G4E_ + n0 + cx;
        #pragma unroll
        for (int j = 0; j < 4; j++) {
            float2 v = unpack2(acc[i][j]);
            Cp[2*j+0] = v.x + bias[n0+cx+2*j+0];
            Cp[2*j+1] = v.y + bias[n0+cx+2*j+1];
        }
    }
}

// ---------------- persistent encoder layer (both dirs, 160 steps, 1 barrier/step) ----------------
// 128 blocks x 128 threads. Block b: dir = b>>6, rowb = (b>>5)&1 (64 rows), ub = b&31 (16 units).
// Tile cols = gate*16 + uu  (self-contained gates -> local epilogue).
__global__ __launch_bounds__(128) void k_encP(int layer, const float* __restrict__ whh_all)
{
    __shared__ float2 As2[16][66];
    __shared__ float  Bs[16][68];
    __shared__ float  gs[64][68];

    const int b   = blockIdx.x;
    const int d   = b >> 6;
    const int rowb= (b >> 5) & 1;
    const int ub  = b & 31;
    const int n0  = rowb * 64;
    const int u0  = ub * 16;
    const int tid = threadIdx.x;
    const int t_c = tid & 15, t_r = tid >> 4;
    const int lcol = tid >> 1, lkq = tid & 1;    // loader: row/col 0..63, k-quarter
    const int wr = ((lcol >> 4) * HE_) + u0 + (lcol & 15);
    const float* Bp = whh_all + ((size_t)d * G4E_ + wr) * HE_;
    float* obase = (layer ? g_enc : g_h1);

    for (int t = 0; t < L_; t++) {
        int t_eff = d ? (L_-1-t) : t;
        if (t > 0) {
            const float* hin = g_eh[t & 1][d];
            const float* Ap = hin + (size_t)(n0 + lcol)*HE_ + lkq*4;
            ull acc[8][2];
            #pragma unroll
            for (int i = 0; i < 8; i++) { acc[i][0]=0ull; acc[i][1]=0ull; }
            for (int kc = 0; kc < HE_; kc += 16) {
                float4 av0 = __ldcg((const float4*)(Ap + kc));
                float4 av1 = __ldcg((const float4*)(Ap + kc + 8));
                float4 bv0 = *(const float4*)(Bp + kc + lkq*4);
                float4 bv1 = *(const float4*)(Bp + kc + lkq*4 + 8);
                __syncthreads();
                int k0 = lkq * 4;
                As2[k0+0][lcol]=make_float2(av0.x,av0.x); As2[k0+1][lcol]=make_float2(av0.y,av0.y);
                As2[k0+2][lcol]=make_float2(av0.z,av0.z); As2[k0+3][lcol]=make_float2(av0.w,av0.w);
                As2[k0+8][lcol]=make_float2(av1.x,av1.x); As2[k0+9][lcol]=make_float2(av1.y,av1.y);
                As2[k0+10][lcol]=make_float2(av1.z,av1.z);As2[k0+11][lcol]=make_float2(av1.w,av1.w);
                Bs[k0+0][lcol]=bv0.x; Bs[k0+1][lcol]=bv0.y; Bs[k0+2][lcol]=bv0.z; Bs[k0+3][lcol]=bv0.w;
                Bs[k0+8][lcol]=bv1.x; Bs[k0+9][lcol]=bv1.y; Bs[k0+10][lcol]=bv1.z; Bs[k0+11][lcol]=bv1.w;
                __syncthreads();
                #pragma unroll
                for (int kk = 0; kk < 16; kk++) {
                    ulonglong2 a01 = *(const ulonglong2*)&As2[kk][t_r*8+0];
                    ulonglong2 a23 = *(const ulonglong2*)&As2[kk][t_r*8+2];
                    ulonglong2 a45 = *(const ulonglong2*)&As2[kk][t_r*8+4];
                    ulonglong2 a67 = *(const ulonglong2*)&As2[kk][t_r*8+6];
                    ulonglong2 bq  = *(const ulonglong2*)&Bs[kk][t_c*4];
                    ull a[8] = {a01.x,a01.y,a23.x,a23.y,a45.x,a45.y,a67.x,a67.y};
                    #pragma unroll
                    for (int i = 0; i < 8; i++) {
                        fma2(acc[i][0], a[i], bq.x);
                        fma2(acc[i][1], a[i], bq.y);
                    }
                }
            }
            #pragma unroll
            for (int i = 0; i < 8; i++) {
                float2 p0 = unpack2(acc[i][0]);
                float2 p1 = unpack2(acc[i][1]);
                gs[t_r*8+i][t_c*4+0] = p0.x;
                gs[t_r*8+i][t_c*4+1] = p0.y;
                gs[t_r*8+i][t_c*4+2] = p1.x;
                gs[t_r*8+i][t_c*4+3] = p1.y;
            }
        }
        __syncthreads();
        // local epilogue: (row = tid>>1, uu = (tid&1)*8 + e)
        {
            int row = tid >> 1;
            int n = n0 + row;
            const float* Gp0 = g_G[d] + ((size_t)t_eff * N_ + n) * G4E_ + u0;
            float* hout = g_eh[1-(t&1)][d];
            float* ob = obase + (size_t)t_eff * (N_*2*HE_) + (size_t)n*(2*HE_) + d*HE_;
            #pragma unroll
            for (int e = 0; e < 8; e++) {
                int uu = (tid & 1) * 8 + e;
                int u = u0 + uu;
                float gi = __ldcs(Gp0 + uu);
                float gf = __ldcs(Gp0 + uu + HE_);
                float gc = __ldcs(Gp0 + uu + 2*HE_);
                float go = __ldcs(Gp0 + uu + 3*HE_);
                float cprev = 0.f;
                if (t > 0) {
                    gi += gs[row][uu];      gf += gs[row][16+uu];
                    gc += gs[row][32+uu];   go += gs[row][48+uu];
                    cprev = g_ec[d][n*HE_ + u];
                }
                float cv = sigf(gf)*cprev + sigf(gi)*tanhf(gc);
                g_ec[d][n*HE_ + u] = cv;
                float hv = sigf(go)*tanhf(cv);
                hout[n*HE_ + u] = hv;
                ob[u] = hv;
            }
        }
        gridbar();
    }
}

// ---------------- decoder init ----------------
__global__ void k_dec_init()
{
    int i = blockIdx.x*blockDim.x + threadIdx.x;
    if (i < N_*HD_) {
        int n = i / HD_, k = i % HD_;
        g_dc[i] = g_enc[(size_t)n*(2*HE_) + HE_ + (k & (HE_-1))];
        g_dh[0][i] = 0.f;
    }
}

// ---------------- persistent decoder (160 steps, fused lstm + logits/softmax/argmax) ----------------
// 128 blocks x 128 threads. GEMM phase: rowb = b>>6, ub = b&63 (16 units of HD).
// Logits phase: block b handles sample n = b.
__global__ __launch_bounds__(128) void k_decP(const float* __restrict__ dwhh,
        const float* __restrict__ dwih, const float* __restrict__ db,
        const float* __restrict__ ow, const float* __restrict__ obv,
        const int* __restrict__ tags, float* __restrict__ out)
{
    __shared__ float2 As2[16][66];
    __shared__ float  Bs[16][68];
    __shared__ float  gs[64][68];
    __shared__ __align__(16) float hs[HD_];
    __shared__ float red[T_];
    __shared__ int   redi[T_];

    const int b   = blockIdx.x;
    const int rowb= b >> 6;
    const int ub  = b & 63;
    const int n0  = rowb * 64;
    const int u0  = ub * 16;
    const int tid = threadIdx.x;
    const int t_c = tid & 15, t_r = tid >> 4;
    const int lcol = tid >> 1, lkq = tid & 1;
    const int wr = ((lcol >> 4) * HD_) + u0 + (lcol & 15);
    const float* Bp = dwhh + (size_t)wr * HD_;

    for (int t = 0; t < L_; t++) {
        const int ph = t & 1;
        // ---- recurrent GEMM (A = h_prev + enc[t]) ----
        {
            const float* hin  = g_dh[ph];
            const float* encT = g_enc + (size_t)t * (N_*HD_);
            size_t aoff = (size_t)(n0 + lcol)*HD_ + lkq*4;
            ull acc[8][2];
            #pragma unroll
            for (int i = 0; i < 8; i++) { acc[i][0]=0ull; acc[i][1]=0ull; }
            for (int kc = 0; kc < HD_; kc += 16) {
                float4 h0 = __ldcg((const float4*)(hin + aoff + kc));
                float4 h1 = __ldcg((const float4*)(hin + aoff + kc + 8));
                float4 e0 = *(const float4*)(encT + aoff + kc);
                float4 e1 = *(const float4*)(encT + aoff + kc + 8);
                float4 av0 = make_float4(h0.x+e0.x, h0.y+e0.y, h0.z+e0.z, h0.w+e0.w);
                float4 av1 = make_float4(h1.x+e1.x, h1.y+e1.y, h1.z+e1.z, h1.w+e1.w);
                float4 bv0 = *(const float4*)(Bp + kc + lkq*4);
                float4 bv1 = *(const float4*)(Bp + kc + lkq*4 + 8);
                __syncthreads();
                int k0 = lkq * 4;
                As2[k0+0][lcol]=make_float2(av0.x,av0.x); As2[k0+1][lcol]=make_float2(av0.y,av0.y);
                As2[k0+2][lcol]=make_float2(av0.z,av0.z); As2[k0+3][lcol]=make_float2(av0.w,av0.w);
                As2[k0+8][lcol]=make_float2(av1.x,av1.x); As2[k0+9][lcol]=make_float2(av1.y,av1.y);
                As2[k0+10][lcol]=make_float2(av1.z,av1.z);As2[k0+11][lcol]=make_float2(av1.w,av1.w);
                Bs[k0+0][lcol]=bv0.x; Bs[k0+1][lcol]=bv0.y; Bs[k0+2][lcol]=bv0.z; Bs[k0+3][lcol]=bv0.w;
                Bs[k0+8][lcol]=bv1.x; Bs[k0+9][lcol]=bv1.y; Bs[k0+10][lcol]=bv1.z; Bs[k0+11][lcol]=bv1.w;
                __syncthreads();
                #pragma unroll
                for (int kk = 0; kk < 16; kk++) {
                    ulonglong2 a01 = *(const ulonglong2*)&As2[kk][t_r*8+0];
                    ulonglong2 a23 = *(const ulonglong2*)&As2[kk][t_r*8+2];
                    ulonglong2 a45 = *(const ulonglong2*)&As2[kk][t_r*8+4];
                    ulonglong2 a67 = *(const ulonglong2*)&As2[kk][t_r*8+6];
                    ulonglong2 bq  = *(const ulonglong2*)&Bs[kk][t_c*4];
                    ull a[8] = {a01.x,a01.y,a23.x,a23.y,a45.x,a45.y,a67.x,a67.y};
                    #pragma unroll
                    for (int i = 0; i < 8; i++) {
                        fma2(acc[i][0], a[i], bq.x);
                        fma2(acc[i][1], a[i], bq.y);
                    }
                }
            }
            #pragma unroll
            for (int i = 0; i < 8; i++) {
                float2 p0 = unpack2(acc[i][0]);
                float2 p1 = unpack2(acc[i][1]);
                gs[t_r*8+i][t_c*4+0] = p0.x;
                gs[t_r*8+i][t_c*4+1] = p0.y;
                gs[t_r*8+i][t_c*4+2] = p1.x;
                gs[t_r*8+i][t_c*4+3] = p1.y;
            }
        }
        __syncthreads();
        // ---- local epilogue ----
        {
            int row = tid >> 1;
            int n = n0 + row;
            int am = 0;
            if (t > 0) am = __ldcg(&g_amax[n]);
            float* hout = g_dh[1-ph];
            #pragma unroll
            for (int e = 0; e < 8; e++) {
                int uu = (tid & 1) * 8 + e;
                int u = u0 + uu;
                float wi0=0.f, wi1=0.f, wi2=0.f, wi3=0.f;
                if (t > 0) {
                    wi0 = __ldg(dwih + (size_t)(u)*T_ + am);
                    wi1 = __ldg(dwih + (size_t)(HD_+u)*T_ + am);
                    wi2 = __ldg(dwih + (size_t)(2*HD_+u)*T_ + am);
                    wi3 = __ldg(dwih + (size_t)(3*HD_+u)*T_ + am);
                }
                float gi = gs[row][uu]    + db[u]         + wi0;
                float gf = gs[row][16+uu] + db[HD_+u]     + wi1;
                float gc = gs[row][32+uu] + db[2*HD_+u]   + wi2;
                float go = gs[row][48+uu] + db[3*HD_+u]   + wi3;
                float cprev = g_dc[n*HD_ + u];
                float cv = sigf(gf)*cprev + sigf(gi)*tanhf(gc);
                g_dc[n*HD_ + u] = cv;
                hout[n*HD_ + u] = sigf(go)*tanhf(cv);
            }
        }
        gridbar();
        // ---- logits / softmax / argmax phase: block b = sample n ----
        {
            const int n = b;
            const int j = tid;
            const float* h = g_dh[1-ph] + (size_t)n * HD_;
            for (int k = tid; k < HD_; k += 128) hs[k] = __ldcg(h + k);
            __syncthreads();
            ull s2[2] = {0ull, 0ull};
            const float* wrow = ow + (size_t)j * HD_;
            #pragma unroll 8
            for (int k = 0; k < HD_; k += 8) {
                ulonglong2 w01 = *(const ulonglong2*)(wrow + k);
                ulonglong2 w23 = *(const ulonglong2*)(wrow + k + 4);
                ulonglong2 h01 = *(const ulonglong2*)&hs[k];
                ulonglong2 h23 = *(const ulonglong2*)&hs[k+4];
                fma2(s2[0], w01.x, h01.x);
                fma2(s2[1], w01.y, h01.y);
                fma2(s2[0], w23.x, h23.x);
                fma2(s2[1], w23.y, h23.y);
            }
            float2 q0 = unpack2(s2[0]);
            float2 q1 = unpack2(s2[1]);
            float acc = obv[j] + ((q0.x + q0.y) + (q1.x + q1.y));
            // max
            red[j] = acc; __syncthreads();
            for (int s = 64; s > 0; s >>= 1) { if (j < s) red[j] = fmaxf(red[j], red[j+s]); __syncthreads(); }
            float mx = red[0]; __syncthreads();
            // sum exp
            float ev = expf(acc - mx);
            red[j] = ev; __syncthreads();
            for (int s = 64; s > 0; s >>= 1) { if (j < s) red[j] += red[j+s]; __syncthreads(); }
            float sum = red[0];
            out[((size_t)n*L_ + t)*T_ + j] = ev / sum;
            int tag = tags[n*L_ + t];
            if (j == tag) g_lterm[t*N_ + n] = -(acc - mx - logf(sum)) / (float)N_;
            __syncthreads();
            // argmax (first index on ties)
            red[j] = acc; redi[j] = j; __syncthreads();
            for (int s = 64; s > 0; s >>= 1) {
                if (j < s) {
                    float o = red[j+s]; int oi = redi[j+s];
                    if (o > red[j] || (o == red[j] && oi < redi[j])) { red[j] = o; redi[j] = oi; }
                }
                __syncthreads();
            }
            if (j == 0) g_amax[n] = redi[0];
        }
        gridbar();
    }
}

// ---------------- deterministic loss reduction ----------------
__global__ void k_loss(float* __restrict__ out)
{
    __shared__ float red[256];
    float s = 0.f;
    for (int i = threadIdx.x; i < L_*N_; i += 256) s += g_lterm[i];
    red[threadIdx.x] = s; __syncthreads();
    for (int st = 128; st > 0; st >>= 1) {
        if (threadIdx.x < st) red[threadIdx.x] += red[threadIdx.x + st];
        __syncthreads();
    }
    if (threadIdx.x == 0) out[(size_t)N_*L_*T_] = red[0];
}

// ---------------- launcher ----------------
extern "C" void kernel_launch(void* const* d_in, const int* in_sizes, int n_in,
                              void* d_out, int out_size)
{
    const int*   ids    = (const int*)  d_in[0];
    const int*   tags   = (const int*)  d_in[1];
    const float* embed  = (const float*)d_in[2];
    const float* e0_wih = (const float*)d_in[3];
    const float* e0_whh = (const float*)d_in[4];
    const float* e0_b   = (const float*)d_in[5];
    const float* e1_wih = (const float*)d_in[6];
    const float* e1_whh = (const float*)d_in[7];
    const float* e1_b   = (const float*)d_in[8];
    const float* dwih   = (const float*)d_in[9];
    const float* dwhh   = (const float*)d_in[10];
    const float* db     = (const float*)d_in[11];
    const float* ow     = (const float*)d_in[12];
    const float* obv    = (const float*)d_in[13];
    float* out = (float*)d_out;

    // 1. embedding
    k_embed<<<(LN_*E_/4 + 255)/256, 256>>>(ids, embed);

    // 2. enc0
    {
        dim3 gg(G4E_/128, LN_/128, 2);
        k_gemm_bias<<<gg, 256>>>(0, e0_wih, e0_b, E_);
    }
    k_encP<<<NB_, 128>>>(0, e0_whh);

    // 3. enc1
    {
        dim3 gg(G4E_/128, LN_/128, 2);
        k_gemm_bias<<<gg, 256>>>(1, e1_wih, e1_b, 2*HE_);
    }
    k_encP<<<NB_, 128>>>(1, e1_whh);

    // 4. decoder (persistent, fused output head)
    k_dec_init<<<(N_*HD_ + 255)/256, 256>>>();
    k_decP<<<NB_, 128>>>(dwhh, dwih, db, ow, obv, tags, out);

    // 5. loss
    k_loss<<<1, 256>>>(out);
}

// round 5
// speedup vs baseline: 1.4291x; 1.4291x over previous
#include <cuda_runtime.h>

typedef unsigned long long ull;

#define N_ 128
#define L_ 160
#define E_ 512
#define HE_ 512
#define HD_ 1024
#define T_ 128
#define LN_ (L_*N_)
#define G4E_ 2048
#define NB_ 128u

// ---------------- scratch (device globals) ----------------
__device__ __align__(16) float g_xs[LN_*E_];
__device__ __align__(16) float g_G[2][(size_t)LN_*G4E_];
__device__ __align__(16) float g_h1[(size_t)LN_*2*HE_];
__device__ __align__(16) float g_enc[(size_t)LN_*2*HE_];
__device__ __align__(16) float g_eh[2][2][N_*HE_];   // [phase][dir]
__device__ __align__(16) float g_ec[2][N_*HE_];      // [dir]
__device__ __align__(16) float g_dh[2][N_*HD_];
__device__ __align__(16) float g_dc[N_*HD_];
__device__ int   g_amax[N_];
__device__ float g_lterm[L_*N_];

__device__ unsigned g_bcnt = 0;
__device__ volatile unsigned g_bgen = 0;

__device__ __forceinline__ void fma2(ull& d, ull a, ull b){
    asm("fma.rn.f32x2 %0, %1, %2, %0;" : "+l"(d) : "l"(a), "l"(b));
}
__device__ __forceinline__ ull dup2(float x){
    ull r; asm("mov.b64 %0, {%1, %1};" : "=l"(r) : "f"(x)); return r;
}
__device__ __forceinline__ float2 unpack2(ull v){
    float2 r; asm("mov.b64 {%0, %1}, %2;" : "=f"(r.x), "=f"(r.y) : "l"(v)); return r;
}
__device__ __forceinline__ float sigf(float x){ return 1.f/(1.f+expf(-x)); }

__device__ __forceinline__ void gridbar(){
    __syncthreads();
    if (threadIdx.x == 0) {
        unsigned g = g_bgen;
        __threadfence();
        if (atomicAdd(&g_bcnt, 1u) == NB_ - 1u) {
            atomicExch(&g_bcnt, 0u);
            __threadfence();
            g_bgen = g + 1u;
        } else {
            while (g_bgen == g) { }
        }
        __threadfence();
    }
    __syncthreads();
}

// ---------------- embedding ----------------
__global__ void k_embed(const int* __restrict__ ids, const float* __restrict__ embed)
{
    int i = blockIdx.x*blockDim.x + threadIdx.x;
    const int tot = LN_*E_/4;
    if (i >= tot) return;
    int e4 = i % (E_/4);
    int ln = i / (E_/4);
    int l = ln / N_, n = ln % N_;
    int id = ids[n*L_ + l];
    reinterpret_cast<float4*>(g_xs)[i] =
        reinterpret_cast<const float4*>(embed + (size_t)id*E_)[e4];
}

// ---------------- big input GEMM (f32x2) ----------------
__global__ __launch_bounds__(256) void k_gemm_bias(int asel, const float* __restrict__ Ball,
                                                   const float* __restrict__ biasall, int K)
{
    const float* A = asel ? g_h1 : g_xs;
    int z = blockIdx.z;
    const float* B = Ball + (size_t)z * G4E_ * K;
    const float* bias = biasall + z * G4E_;
    float* C = g_G[z];
    int m0 = blockIdx.y * 128, n0 = blockIdx.x * 128;
    __shared__ float2 As2[8][132];
    __shared__ float  Bs[8][132];
    int tid = threadIdx.x;
    int lr = tid >> 1, lk = (tid & 1) * 4;
    int ry = (tid >> 4) * 8, cx = (tid & 15) * 8;
    ull acc[8][4];
    #pragma unroll
    for (int i = 0; i < 8; i++)
        #pragma unroll
        for (int j = 0; j < 4; j++) acc[i][j] = 0ull;
    const float* Arow = A + (size_t)(m0+lr)*K + lk;
    const float* Brow = B + (size_t)(n0+lr)*K + lk;
    for (int kc = 0; kc < K; kc += 8) {
        float4 av = *(const float4*)(Arow + kc);
        float4 bv = *(const float4*)(Brow + kc);
        __syncthreads();
        As2[lk+0][lr]=make_float2(av.x,av.x); As2[lk+1][lr]=make_float2(av.y,av.y);
        As2[lk+2][lr]=make_float2(av.z,av.z); As2[lk+3][lr]=make_float2(av.w,av.w);
        Bs[lk+0][lr]=bv.x; Bs[lk+1][lr]=bv.y; Bs[lk+2][lr]=bv.z; Bs[lk+3][lr]=bv.w;
        __syncthreads();
        #pragma unroll
        for (int kk = 0; kk < 8; kk++) {
            ulonglong2 a01 = *(const ulonglong2*)&As2[kk][ry+0];
            ulonglong2 a23 = *(const ulonglong2*)&As2[kk][ry+2];
            ulonglong2 a45 = *(const ulonglong2*)&As2[kk][ry+4];
            ulonglong2 a67 = *(const ulonglong2*)&As2[kk][ry+6];
            ulonglong2 b01 = *(const ulonglong2*)&Bs[kk][cx];
            ulonglong2 b23 = *(const ulonglong2*)&Bs[kk][cx+4];
            ull a[8] = {a01.x,a01.y,a23.x,a23.y,a45.x,a45.y,a67.x,a67.y};
            #pragma unroll
            for (int i = 0; i < 8; i++) {
                fma2(acc[i][0], a[i], b01.x);
                fma2(acc[i][1], a[i], b01.y);
                fma2(acc[i][2], a[i], b23.x);
                fma2(acc[i][3], a[i], b23.y);
            }
        }
    }
    #pragma unroll
    for (int i = 0; i < 8; i++) {
        float* Cp = C + (size_t)(m0+ry+i)*G4E_ + n0 + cx;
        #pragma unroll
        for (int j = 0; j < 4; j++) {
            float2 v = unpack2(acc[i][j]);
            Cp[2*j+0] = v.x + bias[n0+cx+2*j+0];
            Cp[2*j+1] = v.y + bias[n0+cx+2*j+1];
        }
    }
}

// ================= persistent encoder layer =================
__global__ __launch_bounds__(256) void k_encP(int layer, const float* __restrict__ whh_all)
{
    extern __shared__ float sm[];
    float* Bs = sm;                        // [512][34]
    float* As = sm + 512*34;               // [2][16][132]
    float* gs = As + 2*16*132;             // [128][36]

    const int b  = blockIdx.x;
    const int d  = b >> 6;
    const int u0 = (b & 63) * 8;
    const int tid = threadIdx.x;
    const int t_c = tid & 15, t_r = tid >> 4;
    const int lrow = tid >> 1, lk0 = (tid & 1) * 8;

    {
        const float* wb = whh_all + (size_t)d * (4*HE_) * HE_;
        for (int s = tid; s < 32*(HE_/4); s += 256) {
            int c = s / (HE_/4), k4 = s % (HE_/4);
            int wr = (c >> 3) * HE_ + u0 + (c & 7);
            float4 v = *(const float4*)(wb + (size_t)wr*HE_ + k4*4);
            Bs[(k4*4+0)*34 + c] = v.x;
            Bs[(k4*4+1)*34 + c] = v.y;
            Bs[(k4*4+2)*34 + c] = v.z;
            Bs[(k4*4+3)*34 + c] = v.w;
        }
    }
    float* obase = layer ? g_enc : g_h1;
    __syncthreads();

    for (int t = 0; t < L_; t++) {
        const int t_eff = d ? (L_-1-t) : t;
        ull acc[8];
        #pragma unroll
        for (int i = 0; i < 8; i++) acc[i] = 0ull;

        if (t > 0) {
            const float* hin = g_eh[t & 1][d];
            float ra[8];
            {
                float4 h0 = __ldcg((const float4*)(hin + (size_t)lrow*HE_ + lk0));
                float4 h1 = __ldcg((const float4*)(hin + (size_t)lrow*HE_ + lk0 + 4));
                ra[0]=h0.x; ra[1]=h0.y; ra[2]=h0.z; ra[3]=h0.w;
                ra[4]=h1.x; ra[5]=h1.y; ra[6]=h1.z; ra[7]=h1.w;
            }
            #pragma unroll
            for (int i = 0; i < 8; i++) As[(lk0+i)*132 + lrow] = ra[i];
            __syncthreads();
            int buf = 0;
            #pragma unroll 1
            for (int kc = 0; kc < HE_; kc += 16) {
                if (kc + 16 < HE_) {
                    float4 h0 = __ldcg((const float4*)(hin + (size_t)lrow*HE_ + kc+16 + lk0));
                    float4 h1 = __ldcg((const float4*)(hin + (size_t)lrow*HE_ + kc+16 + lk0 + 4));
                    ra[0]=h0.x; ra[1]=h0.y; ra[2]=h0.z; ra[3]=h0.w;
                    ra[4]=h1.x; ra[5]=h1.y; ra[6]=h1.z; ra[7]=h1.w;
                }
                const float* ab = As + buf*2112 + t_r*8;
                const float* bb = Bs + kc*34 + 2*t_c;
                #pragma unroll
                for (int kk = 0; kk < 16; kk++) {
                    float4 a0 = *(const float4*)(ab + kk*132);
                    float4 a1 = *(const float4*)(ab + kk*132 + 4);
                    ull bp = *(const ull*)(bb + kk*34);
                    fma2(acc[0], dup2(a0.x), bp);
                    fma2(acc[1], dup2(a0.y), bp);
                    fma2(acc[2], dup2(a0.z), bp);
                    fma2(acc[3], dup2(a0.w), bp);
                    fma2(acc[4], dup2(a1.x), bp);
                    fma2(acc[5], dup2(a1.y), bp);
                    fma2(acc[6], dup2(a1.z), bp);
                    fma2(acc[7], dup2(a1.w), bp);
                }
                if (kc + 16 < HE_) {
                    int nb = buf ^ 1;
                    #pragma unroll
                    for (int i = 0; i < 8; i++) As[nb*2112 + (lk0+i)*132 + lrow] = ra[i];
                    __syncthreads();
                    buf = nb;
                }
            }
        }
        #pragma unroll
        for (int i = 0; i < 8; i++) {
            float2 v = unpack2(acc[i]);
            gs[(t_r*8+i)*36 + 2*t_c]     = v.x;
            gs[(t_r*8+i)*36 + 2*t_c + 1] = v.y;
        }
        __syncthreads();
        {
            int row = tid >> 1;
            int uu0 = (tid & 1) * 4;
            int n = row;
            const float* Gp = g_G[d] + ((size_t)t_eff*N_ + n)*G4E_ + u0 + uu0;
            float4 Gi = *(const float4*)(Gp);
            float4 Gf = *(const float4*)(Gp + HE_);
            float4 Gc = *(const float4*)(Gp + 2*HE_);
            float4 Go = *(const float4*)(Gp + 3*HE_);
            float4 si = *(const float4*)&gs[row*36 + uu0];
            float4 sf = *(const float4*)&gs[row*36 + 8 + uu0];
            float4 sc = *(const float4*)&gs[row*36 + 16 + uu0];
            float4 so = *(const float4*)&gs[row*36 + 24 + uu0];
            float* cp = &g_ec[d][n*HE_ + u0 + uu0];
            float4 cv = (t > 0) ? *(const float4*)cp : make_float4(0.f,0.f,0.f,0.f);
            float4 cn, hn;
            cn.x = sigf(Gf.x+sf.x)*cv.x + sigf(Gi.x+si.x)*tanhf(Gc.x+sc.x);
            cn.y = sigf(Gf.y+sf.y)*cv.y + sigf(Gi.y+si.y)*tanhf(Gc.y+sc.y);
            cn.z = sigf(Gf.z+sf.z)*cv.z + sigf(Gi.z+si.z)*tanhf(Gc.z+sc.z);
            cn.w = sigf(Gf.w+sf.w)*cv.w + sigf(Gi.w+si.w)*tanhf(Gc.w+sc.w);
            hn.x = sigf(Go.x+so.x)*tanhf(cn.x);
            hn.y = sigf(Go.y+so.y)*tanhf(cn.y);
            hn.z = sigf(Go.z+so.z)*tanhf(cn.z);
            hn.w = sigf(Go.w+so.w)*tanhf(cn.w);
            *(float4*)cp = cn;
            *(float4*)&g_eh[1-(t&1)][d][n*HE_ + u0 + uu0] = hn;
            *(float4*)&obase[(size_t)t_eff*(N_*2*HE_) + (size_t)n*(2*HE_) + d*HE_ + u0 + uu0] = hn;
        }
        gridbar();
    }
}

// ---------------- decoder init ----------------
__global__ void k_dec_init()
{
    int i = blockIdx.x*blockDim.x + threadIdx.x;
    if (i < N_*HD_) {
        int n = i / HD_, k = i % HD_;
        g_dc[i] = g_enc[(size_t)n*(2*HE_) + HE_ + (k & (HE_-1))];
        g_dh[0][i] = 0.f;
    }
}

// ================= persistent decoder =================
__global__ __launch_bounds__(256) void k_decP(const float* __restrict__ dwhh,
        const float* __restrict__ dwih, const float* __restrict__ db,
        const float* __restrict__ ow, const float* __restrict__ obv,
        const int* __restrict__ tags, float* __restrict__ out)
{
    extern __shared__ float sm[];
    float* Bs = sm;                        // [1024][34]
    float* As = sm + 1024*34;              // [2][16][132]
    float* gs = As + 2*16*132;             // [128][36]
    float* hs  = As;                       // logits overlay [1024]
    float* red = As + 1024;                // [256]
    int*  redi = (int*)(red + 256);        // [128]

    const int b  = blockIdx.x;
    const int u0 = b * 8;
    const int tid = threadIdx.x;
    const int t_c = tid & 15, t_r = tid >> 4;
    const int lrow = tid >> 1, lk0 = (tid & 1) * 8;

    for (int s = tid; s < 32*(HD_/4); s += 256) {
        int c = s / (HD_/4), k4 = s % (HD_/4);
        int wr = (c >> 3) * HD_ + u0 + (c & 7);
        float4 v = *(const float4*)(dwhh + (size_t)wr*HD_ + k4*4);
        Bs[(k4*4+0)*34 + c] = v.x;
        Bs[(k4*4+1)*34 + c] = v.y;
        Bs[(k4*4+2)*34 + c] = v.z;
        Bs[(k4*4+3)*34 + c] = v.w;
    }
    __syncthreads();

    for (int t = 0; t < L_; t++) {
        const int ph = t & 1;
        ull acc[8];
        #pragma unroll
        for (int i = 0; i < 8; i++) acc[i] = 0ull;
        {
            const float* hin  = g_dh[ph];
            const float* encT = g_enc + (size_t)t * (N_*HD_);
            const size_t abase = (size_t)lrow*HD_ + lk0;
            float ra[8];
            {
                float4 h0 = __ldcg((const float4*)(hin + abase));
                float4 h1 = __ldcg((const float4*)(hin + abase + 4));
                float4 e0 = *(const float4*)(encT + abase);
                float4 e1 = *(const float4*)(encT + abase + 4);
                ra[0]=h0.x+e0.x; ra[1]=h0.y+e0.y; ra[2]=h0.z+e0.z; ra[3]=h0.w+e0.w;
                ra[4]=h1.x+e1.x; ra[5]=h1.y+e1.y; ra[6]=h1.z+e1.z; ra[7]=h1.w+e1.w;
            }
            #pragma unroll
            for (int i = 0; i < 8; i++) As[(lk0+i)*132 + lrow] = ra[i];
            __syncthreads();
            int buf = 0;
            #pragma unroll 1
            for (int kc = 0; kc < HD_; kc += 16) {
                if (kc + 16 < HD_) {
                    float4 h0 = __ldcg((const float4*)(hin + abase + kc+16));
                    float4 h1 = __ldcg((const float4*)(hin + abase + kc+16 + 4));
                    float4 e0 = *(const float4*)(encT + abase + kc+16);
                    float4 e1 = *(const float4*)(encT + abase + kc+16 + 4);
                    ra[0]=h0.x+e0.x; ra[1]=h0.y+e0.y; ra[2]=h0.z+e0.z; ra[3]=h0.w+e0.w;
                    ra[4]=h1.x+e1.x; ra[5]=h1.y+e1.y; ra[6]=h1.z+e1.z; ra[7]=h1.w+e1.w;
                }
                const float* ab = As + buf*2112 + t_r*8;
                const float* bb = Bs + kc*34 + 2*t_c;
                #pragma unroll
                for (int kk = 0; kk < 16; kk++) {
                    float4 a0 = *(const float4*)(ab + kk*132);
                    float4 a1 = *(const float4*)(ab + kk*132 + 4);
                    ull bp = *(const ull*)(bb + kk*34);
                    fma2(acc[0], dup2(a0.x), bp);
                    fma2(acc[1], dup2(a0.y), bp);
                    fma2(acc[2], dup2(a0.z), bp);
                    fma2(acc[3], dup2(a0.w), bp);
                    fma2(acc[4], dup2(a1.x), bp);
                    fma2(acc[5], dup2(a1.y), bp);
                    fma2(acc[6], dup2(a1.z), bp);
                    fma2(acc[7], dup2(a1.w), bp);
                }
                if (kc + 16 < HD_) {
                    int nb = buf ^ 1;
                    #pragma unroll
                    for (int i = 0; i < 8; i++) As[nb*2112 + (lk0+i)*132 + lrow] = ra[i];
                    __syncthreads();
                    buf = nb;
                }
            }
        }
        #pragma unroll
        for (int i = 0; i < 8; i++) {
            float2 v = unpack2(acc[i]);
            gs[(t_r*8+i)*36 + 2*t_c]     = v.x;
            gs[(t_r*8+i)*36 + 2*t_c + 1] = v.y;
        }
        __syncthreads();
        {
            int row = tid >> 1;
            int uu0 = (tid & 1) * 4;
            int n = row;
            int am = (t > 0) ? __ldcg(&g_amax[n]) : 0;
            float4 si = *(const float4*)&gs[row*36 + uu0];
            float4 sf = *(const float4*)&gs[row*36 + 8 + uu0];
            float4 sc = *(const float4*)&gs[row*36 + 16 + uu0];
            float4 so = *(const float4*)&gs[row*36 + 24 + uu0];
            float4 bi = *(const float4*)(db + u0 + uu0);
            float4 bf = *(const float4*)(db + HD_ + u0 + uu0);
            float4 bc = *(const float4*)(db + 2*HD_ + u0 + uu0);
            float4 bo = *(const float4*)(db + 3*HD_ + u0 + uu0);
            float wi[4][4];
            #pragma unroll
            for (int g = 0; g < 4; g++)
                #pragma unroll
                for (int e = 0; e < 4; e++)
                    wi[g][e] = (t > 0) ? __ldg(dwih + (size_t)(g*HD_ + u0 + uu0 + e)*T_ + am) : 0.f;
            float gi[4] = {si.x+bi.x+wi[0][0], si.y+bi.y+wi[0][1], si.z+bi.z+wi[0][2], si.w+bi.w+wi[0][3]};
            float gf[4] = {sf.x+bf.x+wi[1][0], sf.y+bf.y+wi[1][1], sf.z+bf.z+wi[1][2], sf.w+bf.w+wi[1][3]};
            float gc[4] = {sc.x+bc.x+wi[2][0], sc.y+bc.y+wi[2][1], sc.z+bc.z+wi[2][2], sc.w+bc.w+wi[2][3]};
            float go[4] = {so.x+bo.x+wi[3][0], so.y+bo.y+wi[3][1], so.z+bo.z+wi[3][2], so.w+bo.w+wi[3][3]};
            float* cp = &g_dc[n*HD_ + u0 + uu0];
            float4 cv = *(const float4*)cp;
            float4 cn, hn;
            cn.x = sigf(gf[0])*cv.x + sigf(gi[0])*tanhf(gc[0]);
            cn.y = sigf(gf[1])*cv.y + sigf(gi[1])*tanhf(gc[1]);
            cn.z = sigf(gf[2])*cv.z + sigf(gi[2])*tanhf(gc[2]);
            cn.w = sigf(gf[3])*cv.w + sigf(gi[3])*tanhf(gc[3]);
            hn.x = sigf(go[0])*tanhf(cn.x);
            hn.y = sigf(go[1])*tanhf(cn.y);
            hn.z = sigf(go[2])*tanhf(cn.z);
            hn.w = sigf(go[3])*tanhf(cn.w);
            *(float4*)cp = cn;
            *(float4*)&g_dh[1-ph][n*HD_ + u0 + uu0] = hn;
        }
        gridbar();
        // ---- logits / softmax / argmax: block b = sample n ----
        {
            const int n = b;
            const int j = tid & 127;
            const int half = tid >> 7;
            const float* hsrc = g_dh[1-ph] + (size_t)n*HD_;
            for (int k = tid; k < HD_; k += 256) hs[k] = __ldcg(hsrc + k);
            __syncthreads();
            ull s0 = 0ull, s1 = 0ull;
            const float* wrow = ow + (size_t)j*HD_ + half*512;
            const float* hh = hs + half*512;
            #pragma unroll 8
            for (int k = 0; k < 512; k += 8) {
                ulonglong2 w01 = *(const ulonglong2*)(wrow + k);
                ulonglong2 w23 = *(const ulonglong2*)(wrow + k + 4);
                ulonglong2 h01 = *(const ulonglong2*)(hh + k);
                ulonglong2 h23 = *(const ulonglong2*)(hh + k + 4);
                fma2(s0, w01.x, h01.x);
                fma2(s1, w01.y, h01.y);
                fma2(s0, w23.x, h23.x);
                fma2(s1, w23.y, h23.y);
            }
            float2 q0 = unpack2(s0), q1 = unpack2(s1);
            red[tid] = (q0.x + q0.y) + (q1.x + q1.y);
            __syncthreads();
            float accv = obv[j] + red[j] + red[j+128];
            __syncthreads();
            if (half == 0) red[j] = accv;
            __syncthreads();
            for (int s = 64; s > 0; s >>= 1) { if (tid < s) red[tid] = fmaxf(red[tid], red[tid+s]); __syncthreads(); }
            float mx = red[0]; __syncthreads();
            float ev = expf(accv - mx);
            if (half == 0) red[j] = ev;
            __syncthreads();
            for (int s = 64; s > 0; s >>= 1) { if (tid < s) red[tid] += red[tid+s]; __syncthreads(); }
            float sum = red[0];
            if (half == 0) out[((size_t)n*L_ + t)*T_ + j] = ev / sum;
            int tag = tags[n*L_ + t];
            if (tid == tag) g_lterm[t*N_ + n] = -(accv - mx - logf(sum)) / (float)N_;
            __syncthreads();
            if (half == 0) { red[j] = accv; redi[j] = j; }
            __syncthreads();
            for (int s = 64; s > 0; s >>= 1) {
                if (tid < s) {
                    float o = red[tid+s]; int oi = redi[tid+s];
                    if (o > red[tid] || (o == red[tid] && oi < redi[tid])) { red[tid] = o; redi[tid] = oi; }
                }
                __syncthreads();
            }
            if (tid == 0) g_amax[n] = redi[0];
        }
        gridbar();
    }
}

// ---------------- deterministic loss reduction ----------------
__global__ void k_loss(float* __restrict__ out)
{
    __shared__ float red[256];
    float s = 0.f;
    for (int i = threadIdx.x; i < L_*N_; i += 256) s += g_lterm[i];
    red[threadIdx.x] = s; __syncthreads();
    for (int st = 128; st > 0; st >>= 1) {
        if (threadIdx.x < st) red[threadIdx.x] += red[threadIdx.x + st];
        __syncthreads();
    }
    if (threadIdx.x == 0) out[(size_t)N_*L_*T_] = red[0];
}

// ---------------- launcher ----------------
#define ENC_SMEM ((512*34 + 2*16*132 + 128*36)*4)
#define DEC_SMEM ((1024*34 + 2*16*132 + 128*36)*4)

extern "C" void kernel_launch(void* const* d_in, const int* in_sizes, int n_in,
                              void* d_out, int out_size)
{
    const int*   ids    = (const int*)  d_in[0];
    const int*   tags   = (const int*)  d_in[1];
    const float* embed  = (const float*)d_in[2];
    const float* e0_wih = (const float*)d_in[3];
    const float* e0_whh = (const float*)d_in[4];
    const float* e0_b   = (const float*)d_in[5];
    const float* e1_wih = (const float*)d_in[6];
    const float* e1_whh = (const float*)d_in[7];
    const float* e1_b   = (const float*)d_in[8];
    const float* dwih   = (const float*)d_in[9];
    const float* dwhh   = (const float*)d_in[10];
    const float* db     = (const float*)d_in[11];
    const float* ow     = (const float*)d_in[12];
    const float* obv    = (const float*)d_in[13];
    float* out = (float*)d_out;

    cudaFuncSetAttribute(k_encP, cudaFuncAttributeMaxDynamicSharedMemorySize, ENC_SMEM);
    cudaFuncSetAttribute(k_decP, cudaFuncAttributeMaxDynamicSharedMemorySize, DEC_SMEM);

    // 1. embedding
    k_embed<<<(LN_*E_/4 + 255)/256, 256>>>(ids, embed);

    // 2. enc0
    {
        dim3 gg(G4E_/128, LN_/128, 2);
        k_gemm_bias<<<gg, 256>>>(0, e0_wih, e0_b, E_);
    }
    k_encP<<<NB_, 256, ENC_SMEM>>>(0, e0_whh);

    // 3. enc1
    {
        dim3 gg(G4E_/128, LN_/128, 2);
        k_gemm_bias<<<gg, 256>>>(1, e1_wih, e1_b, 2*HE_);
    }
    k_encP<<<NB_, 256, ENC_SMEM>>>(1, e1_whh);

    // 4. decoder
    k_dec_init<<<(N_*HD_ + 255)/256, 256>>>();
    k_decP<<<NB_, 256, DEC_SMEM>>>(dwhh, dwih, db, ow, obv, tags, out);

    // 5. loss
    k_loss<<<1, 256>>>(out);
}